// round 10
// baseline (speedup 1.0000x reference)
#include <cuda_runtime.h>

#define N_NODES 20000
#define N_PAD   20480          // 1024 threads * 20 each
#define N_EDGES 640000
#define D       128
#define NGRAPH  64

// ---------------- scratch (device globals) ---------------------------------
__device__ float g_Y [N_NODES * D];
__device__ float g_H [N_NODES * D];
__device__ float g_H2[N_NODES * D];
__device__ __align__(16) int g_deg[N_PAD];        // padded, zero-filled
__device__ __align__(16) int g_off[N_PAD + 4];    // padded
__device__ __align__(16) int g_rank[N_EDGES];
__device__ int2  g_srcw[N_EDGES];                 // packed (src, bit-cast weight)

// ---------------- CSR build ------------------------------------------------
__global__ void k_zero() {
    int i = blockIdx.x * blockDim.x + threadIdx.x;
    if (i < N_PAD) g_deg[i] = 0;
}

// 1 edge/thread (max warp count hides ATOMG latency); rank captured here
__global__ void k_hist(const int* __restrict__ ei) {
    int e = blockIdx.x * blockDim.x + threadIdx.x;
    if (e < N_EDGES) {
        int dst = ei[N_EDGES + e];
        g_rank[e] = atomicAdd(&g_deg[dst], 1);
    }
}

// warp-shuffle scan: 5xLDG.128, 2 barriers, 5xSTG.128 per thread
__global__ void k_scan() {
    __shared__ int wsum[32];
    int t = threadIdx.x;
    int lane = t & 31, w = t >> 5;

    int4 v[5];
    #pragma unroll
    for (int i = 0; i < 5; i++)
        v[i] = *(const int4*)&g_deg[t * 20 + i * 4];

    int loc[20];
    int s = 0;
    #pragma unroll
    for (int i = 0; i < 5; i++) {
        loc[i * 4 + 0] = s; s += v[i].x;
        loc[i * 4 + 1] = s; s += v[i].y;
        loc[i * 4 + 2] = s; s += v[i].z;
        loc[i * 4 + 3] = s; s += v[i].w;
    }
    // warp inclusive scan of thread totals
    int inc = s;
    #pragma unroll
    for (int d = 1; d < 32; d <<= 1) {
        int n = __shfl_up_sync(0xffffffffu, inc, d);
        if (lane >= d) inc += n;
    }
    if (lane == 31) wsum[w] = inc;
    __syncthreads();
    if (w == 0) {
        int ws = wsum[lane];
        int winc = ws;
        #pragma unroll
        for (int d = 1; d < 32; d <<= 1) {
            int n = __shfl_up_sync(0xffffffffu, winc, d);
            if (lane >= d) winc += n;
        }
        wsum[lane] = winc - ws;          // exclusive warp prefix
    }
    __syncthreads();
    int off = wsum[w] + (inc - s);       // exclusive prefix for this thread

    int4 o[5];
    #pragma unroll
    for (int i = 0; i < 5; i++) {
        o[i].x = off + loc[i * 4 + 0];
        o[i].y = off + loc[i * 4 + 1];
        o[i].z = off + loc[i * 4 + 2];
        o[i].w = off + loc[i * 4 + 3];
    }
    #pragma unroll
    for (int i = 0; i < 5; i++)
        *(int4*)&g_off[t * 20 + i * 4] = o[i];
    // g_off[20000] (the sentinel = total edges) is written by thread 1000,
    // exact because padding degrees are zero.
}

// atomic-free scatter: p = off[dst] + rank[e]; 4 edges/thread for MLP
__global__ void k_place(const int* __restrict__ ei, const float* __restrict__ ew) {
    int e0 = (blockIdx.x * blockDim.x + threadIdx.x) * 4;
    if (e0 < N_EDGES) {
        int4   dd = *(const int4*)&ei[N_EDGES + e0];
        int4   ss = *(const int4*)&ei[e0];
        float4 ww = *(const float4*)&ew[e0];
        int4   rr = *(const int4*)&g_rank[e0];
        int p0 = g_off[dd.x] + rr.x;
        int p1 = g_off[dd.y] + rr.y;
        int p2 = g_off[dd.z] + rr.z;
        int p3 = g_off[dd.w] + rr.w;
        g_srcw[p0] = make_int2(ss.x, __float_as_int(ww.x));
        g_srcw[p1] = make_int2(ss.y, __float_as_int(ww.y));
        g_srcw[p2] = make_int2(ss.z, __float_as_int(ww.z));
        g_srcw[p3] = make_int2(ss.w, __float_as_int(ww.w));
    }
}

// ---------------- fused dual GEMM with packed f32x2 FFMA -------------------
__device__ __forceinline__ void ffma2(unsigned long long& d,
                                      unsigned long long a,
                                      unsigned long long b) {
    asm("fma.rn.f32x2 %0, %1, %2, %0;" : "+l"(d) : "l"(a), "l"(b));
}
__device__ __forceinline__ unsigned long long bcast2(float x) {
    unsigned long long r;
    asm("mov.b64 %0, {%1, %1};" : "=l"(r) : "f"(x));
    return r;
}

#define XS_STRIDE 36

template <int LAYER>   // 0: x -> (g_Y, g_H) | 1: g_H -> (g_Y, g_H2)
__global__ void __launch_bounds__(256, 2)
k_gemm2(const float* __restrict__ Xext,
        const float* __restrict__ Wa,
        const float* __restrict__ Wb,
        const float* __restrict__ bias) {
    const float* X  = (LAYER == 0) ? Xext : g_H;
    float* Ya = g_Y;
    float* Yb = (LAYER == 0) ? g_H : g_H2;

    __shared__ float Xs [64 * XS_STRIDE];
    __shared__ float Was[32 * 128];
    __shared__ float Wbs[32 * 128];

    int tid = threadIdx.x;
    int tx = tid & 15, ty = tid >> 4;
    int row0 = blockIdx.x * 64;

    unsigned long long accA[4][4], accB[4][4];
    #pragma unroll
    for (int r = 0; r < 4; r++)
        #pragma unroll
        for (int p = 0; p < 4; p++) { accA[r][p] = 0ull; accB[r][p] = 0ull; }

    for (int kt = 0; kt < 4; kt++) {
        int k0 = kt * 32;
        for (int i = tid; i < 64 * 8; i += 256) {
            int r = i >> 3, kk = i & 7;
            int gr = row0 + r;
            float4 v = make_float4(0.f, 0.f, 0.f, 0.f);
            if (gr < N_NODES) v = *(const float4*)&X[gr * D + k0 + kk * 4];
            *(float4*)&Xs[r * XS_STRIDE + kk * 4] = v;
        }
        {
            int c = tid & 127, half = tid >> 7;
            #pragma unroll
            for (int q = 0; q < 4; q++) {
                int kk4 = half * 4 + q;
                float4 va = *(const float4*)&Wa[c * D + k0 + kk4 * 4];
                float4 vb = *(const float4*)&Wb[c * D + k0 + kk4 * 4];
                Was[(kk4 * 4 + 0) * 128 + c] = va.x;
                Was[(kk4 * 4 + 1) * 128 + c] = va.y;
                Was[(kk4 * 4 + 2) * 128 + c] = va.z;
                Was[(kk4 * 4 + 3) * 128 + c] = va.w;
                Wbs[(kk4 * 4 + 0) * 128 + c] = vb.x;
                Wbs[(kk4 * 4 + 1) * 128 + c] = vb.y;
                Wbs[(kk4 * 4 + 2) * 128 + c] = vb.z;
                Wbs[(kk4 * 4 + 3) * 128 + c] = vb.w;
            }
        }
        __syncthreads();

        #pragma unroll
        for (int kk4 = 0; kk4 < 8; kk4++) {
            float4 xr[4];
            #pragma unroll
            for (int r = 0; r < 4; r++)
                xr[r] = *(float4*)&Xs[(ty * 4 + r) * XS_STRIDE + kk4 * 4];

            #define K_STEP(J, COMP)                                                        \
            {                                                                              \
                int kk = kk4 * 4 + J;                                                      \
                unsigned long long xx[4];                                                  \
                xx[0] = bcast2(xr[0].COMP); xx[1] = bcast2(xr[1].COMP);                    \
                xx[2] = bcast2(xr[2].COMP); xx[3] = bcast2(xr[3].COMP);                    \
                _Pragma("unroll")                                                          \
                for (int p = 0; p < 4; p++) {                                              \
                    unsigned long long wa = *(const unsigned long long*)&Was[kk * 128 + 32 * p + 2 * tx]; \
                    unsigned long long wb = *(const unsigned long long*)&Wbs[kk * 128 + 32 * p + 2 * tx]; \
                    _Pragma("unroll")                                                      \
                    for (int r = 0; r < 4; r++) {                                          \
                        ffma2(accA[r][p], xx[r], wa);                                      \
                        ffma2(accB[r][p], xx[r], wb);                                      \
                    }                                                                      \
                }                                                                          \
            }
            K_STEP(0, x)
            K_STEP(1, y)
            K_STEP(2, z)
            K_STEP(3, w)
            #undef K_STEP
        }
        __syncthreads();
    }

    #pragma unroll
    for (int p = 0; p < 4; p++) {
        int c = 32 * p + 2 * tx;
        float b0 = bias[c], b1 = bias[c + 1];
        #pragma unroll
        for (int r = 0; r < 4; r++) {
            int gr = row0 + ty * 4 + r;
            if (gr < N_NODES) {
                float a0, a1;
                asm("mov.b64 {%0, %1}, %2;" : "=f"(a0), "=f"(a1) : "l"(accA[r][p]));
                *(float2*)&Ya[gr * D + c] = make_float2(a0, a1);
                asm("mov.b64 {%0, %1}, %2;" : "=f"(a0), "=f"(a1) : "l"(accB[r][p]));
                *(float2*)&Yb[gr * D + c] = make_float2(a0 + b0, a1 + b1);
            }
        }
    }
}

// ---------------- edge aggregation: H[i] += sum_e w_e * Y[src_e] -----------
template <int MODE>   // 1: into g_H with relu; 2: into g_H2
__global__ void k_agg() {
    const float* Y = g_Y;
    float* H = (MODE == 1) ? g_H : g_H2;
    int node = (blockIdx.x * blockDim.x + threadIdx.x) >> 5;
    int lane = threadIdx.x & 31;
    if (node >= N_NODES) return;
    int beg = g_off[node], end = g_off[node + 1];
    float4 acc = *(float4*)&H[node * D + lane * 4];
    int e = beg;
    for (; e + 8 <= end; e += 8) {
        int2 p[8];
        #pragma unroll
        for (int j = 0; j < 8; j++) p[j] = g_srcw[e + j];
        float4 v[8];
        #pragma unroll
        for (int j = 0; j < 8; j++) v[j] = *(const float4*)&Y[p[j].x * D + lane * 4];
        #pragma unroll
        for (int j = 0; j < 8; j++) {
            float w = __int_as_float(p[j].y);
            acc.x += w * v[j].x; acc.y += w * v[j].y;
            acc.z += w * v[j].z; acc.w += w * v[j].w;
        }
    }
    for (; e < end; e++) {
        int2 pe = g_srcw[e];
        float w = __int_as_float(pe.y);
        float4 v = *(const float4*)&Y[pe.x * D + lane * 4];
        acc.x += w * v.x; acc.y += w * v.y; acc.z += w * v.z; acc.w += w * v.w;
    }
    if (MODE == 1) {
        acc.x = fmaxf(acc.x, 0.f); acc.y = fmaxf(acc.y, 0.f);
        acc.z = fmaxf(acc.z, 0.f); acc.w = fmaxf(acc.w, 0.f);
    }
    *(float4*)&H[node * D + lane * 4] = acc;
}

// ---------------- mean-pool + linear head + relu ---------------------------
__global__ void k_pool(const int* __restrict__ batch,
                       const float* __restrict__ Wlin, const float* __restrict__ blin,
                       float* __restrict__ out) {
    const float* H2 = g_H2;
    int g = blockIdx.x;
    int c = threadIdx.x;   // 128 threads
    int lo = 0, hi = N_NODES;
    while (lo < hi) { int m = (lo + hi) >> 1; if (batch[m] < g) lo = m + 1; else hi = m; }
    int start = lo;
    lo = 0; hi = N_NODES;
    while (lo < hi) { int m = (lo + hi) >> 1; if (batch[m] < g + 1) lo = m + 1; else hi = m; }
    int end = lo;

    // 4 independent accumulators to expose load MLP
    float a0 = 0.f, a1 = 0.f, a2 = 0.f, a3 = 0.f;
    int n = start;
    for (; n + 4 <= end; n += 4) {
        a0 += H2[n * D + c];
        a1 += H2[(n + 1) * D + c];
        a2 += H2[(n + 2) * D + c];
        a3 += H2[(n + 3) * D + c];
    }
    for (; n < end; n++) a0 += H2[n * D + c];
    float acc = (a0 + a1) + (a2 + a3);
    float cnt = (float)(end - start);
    float pooled = acc / fmaxf(cnt, 1.f);
    float v = pooled * Wlin[c];

    __shared__ float red[128];
    red[c] = v;
    __syncthreads();
    for (int s = 64; s > 0; s >>= 1) {
        if (c < s) red[c] += red[c + s];
        __syncthreads();
    }
    if (c == 0) out[g] = fmaxf(red[0] + blin[0], 0.f);
}

// ---------------- launch ---------------------------------------------------
extern "C" void kernel_launch(void* const* d_in, const int* in_sizes, int n_in,
                              void* d_out, int out_size) {
    const float* x      = (const float*)d_in[0];
    const int*   ei     = (const int*)d_in[1];
    const int*   batch  = (const int*)d_in[2];
    const float* ew     = (const float*)d_in[3];
    const float* W1_rel = (const float*)d_in[4];
    const float* b1     = (const float*)d_in[5];
    const float* W1_root= (const float*)d_in[6];
    const float* W3_rel = (const float*)d_in[7];
    const float* b3     = (const float*)d_in[8];
    const float* W3_root= (const float*)d_in[9];
    const float* Wlin   = (const float*)d_in[10];
    const float* blin   = (const float*)d_in[11];
    float*       out    = (float*)d_out;

    int gb = (N_NODES + 63) / 64;

    cudaStream_t side = nullptr;
    cudaEvent_t evFork = nullptr, evJoin = nullptr;
    bool forked = (cudaStreamCreateWithFlags(&side, cudaStreamNonBlocking) == cudaSuccess) &&
                  (cudaEventCreateWithFlags(&evFork, cudaEventDisableTiming) == cudaSuccess) &&
                  (cudaEventCreateWithFlags(&evJoin, cudaEventDisableTiming) == cudaSuccess);

    if (forked && cudaEventRecord(evFork, 0) == cudaSuccess &&
        cudaStreamWaitEvent(side, evFork, 0) == cudaSuccess) {
        // Branch A (main): layer-1 dual GEMM
        k_gemm2<0><<<gb, 256>>>(x, W1_rel, W1_root, b1);
        // Branch B (side): CSR build
        k_zero <<<(N_PAD + 255) / 256, 256, 0, side>>>();
        k_hist <<<(N_EDGES + 255) / 256, 256, 0, side>>>(ei);
        k_scan <<<1, 1024, 0, side>>>();
        k_place<<<(N_EDGES / 4 + 255) / 256, 256, 0, side>>>(ei, ew);
        cudaEventRecord(evJoin, side);
        cudaStreamWaitEvent(0, evJoin, 0);
    } else {
        k_zero <<<(N_PAD + 255) / 256, 256>>>();
        k_hist <<<(N_EDGES + 255) / 256, 256>>>(ei);
        k_scan <<<1, 1024>>>();
        k_place<<<(N_EDGES / 4 + 255) / 256, 256>>>(ei, ew);
        k_gemm2<0><<<gb, 256>>>(x, W1_rel, W1_root, b1);
    }

    // layer 1 aggregation (needs CSR + gemm1)
    k_agg<1><<<(N_NODES * 32 + 255) / 256, 256>>>();

    // layer 2
    k_gemm2<1><<<gb, 256>>>(nullptr, W3_rel, W3_root, b3);
    k_agg<2><<<(N_NODES * 32 + 255) / 256, 256>>>();

    // pool + head
    k_pool<<<NGRAPH, 128>>>(batch, Wlin, blin, out);
}

// round 12
// speedup vs baseline: 1.0701x; 1.0701x over previous
#include <cuda_runtime.h>
#include <cuda_fp16.h>

#define N_NODES 20000
#define N_PAD   20480          // 1024 threads * 20 each
#define N_EDGES 640000
#define D       128
#define NGRAPH  64

// ---------------- scratch (device globals) ---------------------------------
__device__ __half2 g_Yh[N_NODES * (D / 2)];          // fp16 messages (gather stream)
__device__ float g_H [N_NODES * D];
__device__ float g_H2[N_NODES * D];
__device__ __align__(16) int g_deg[N_PAD];
__device__ __align__(16) int g_off[N_PAD + 4];
__device__ __align__(16) int g_rank[N_EDGES];
__device__ int2  g_srcw[N_EDGES];                    // packed (src, bit-cast weight)

// ---------------- CSR build ------------------------------------------------
__global__ void k_zero() {
    int i = blockIdx.x * blockDim.x + threadIdx.x;
    if (i < N_PAD) g_deg[i] = 0;
}

__global__ void k_hist(const int* __restrict__ ei) {
    int e = blockIdx.x * blockDim.x + threadIdx.x;
    if (e < N_EDGES) {
        int dst = ei[N_EDGES + e];
        g_rank[e] = atomicAdd(&g_deg[dst], 1);
    }
}

// warp-shuffle scan: 5xLDG.128, 2 barriers, 5xSTG.128 per thread
__global__ void k_scan() {
    __shared__ int wsum[32];
    int t = threadIdx.x;
    int lane = t & 31, w = t >> 5;

    int4 v[5];
    #pragma unroll
    for (int i = 0; i < 5; i++)
        v[i] = *(const int4*)&g_deg[t * 20 + i * 4];

    int loc[20];
    int s = 0;
    #pragma unroll
    for (int i = 0; i < 5; i++) {
        loc[i * 4 + 0] = s; s += v[i].x;
        loc[i * 4 + 1] = s; s += v[i].y;
        loc[i * 4 + 2] = s; s += v[i].z;
        loc[i * 4 + 3] = s; s += v[i].w;
    }
    int inc = s;
    #pragma unroll
    for (int d = 1; d < 32; d <<= 1) {
        int n = __shfl_up_sync(0xffffffffu, inc, d);
        if (lane >= d) inc += n;
    }
    if (lane == 31) wsum[w] = inc;
    __syncthreads();
    if (w == 0) {
        int ws = wsum[lane];
        int winc = ws;
        #pragma unroll
        for (int d = 1; d < 32; d <<= 1) {
            int n = __shfl_up_sync(0xffffffffu, winc, d);
            if (lane >= d) winc += n;
        }
        wsum[lane] = winc - ws;
    }
    __syncthreads();
    int off = wsum[w] + (inc - s);

    int4 o[5];
    #pragma unroll
    for (int i = 0; i < 5; i++) {
        o[i].x = off + loc[i * 4 + 0];
        o[i].y = off + loc[i * 4 + 1];
        o[i].z = off + loc[i * 4 + 2];
        o[i].w = off + loc[i * 4 + 3];
    }
    #pragma unroll
    for (int i = 0; i < 5; i++)
        *(int4*)&g_off[t * 20 + i * 4] = o[i];
}

// atomic-free scatter: p = off[dst] + rank[e]
__global__ void k_place(const int* __restrict__ ei, const float* __restrict__ ew) {
    int e0 = (blockIdx.x * blockDim.x + threadIdx.x) * 4;
    if (e0 < N_EDGES) {
        int4   dd = *(const int4*)&ei[N_EDGES + e0];
        int4   ss = *(const int4*)&ei[e0];
        float4 ww = *(const float4*)&ew[e0];
        int4   rr = *(const int4*)&g_rank[e0];
        int p0 = g_off[dd.x] + rr.x;
        int p1 = g_off[dd.y] + rr.y;
        int p2 = g_off[dd.z] + rr.z;
        int p3 = g_off[dd.w] + rr.w;
        g_srcw[p0] = make_int2(ss.x, __float_as_int(ww.x));
        g_srcw[p1] = make_int2(ss.y, __float_as_int(ww.y));
        g_srcw[p2] = make_int2(ss.z, __float_as_int(ww.z));
        g_srcw[p3] = make_int2(ss.w, __float_as_int(ww.w));
    }
}

// ---------------- fused dual GEMM with packed f32x2 FFMA -------------------
__device__ __forceinline__ void ffma2(unsigned long long& d,
                                      unsigned long long a,
                                      unsigned long long b) {
    asm("fma.rn.f32x2 %0, %1, %2, %0;" : "+l"(d) : "l"(a), "l"(b));
}
__device__ __forceinline__ unsigned long long bcast2(float x) {
    unsigned long long r;
    asm("mov.b64 %0, {%1, %1};" : "=l"(r) : "f"(x));
    return r;
}

#define XS_STRIDE 36

template <int LAYER>   // 0: x -> (g_Yh, g_H) | 1: g_H -> (g_Yh, g_H2)
__global__ void __launch_bounds__(256, 2)
k_gemm2(const float* __restrict__ Xext,
        const float* __restrict__ Wa,
        const float* __restrict__ Wb,
        const float* __restrict__ bias) {
    const float* X  = (LAYER == 0) ? Xext : g_H;
    float* Yb = (LAYER == 0) ? g_H : g_H2;

    __shared__ float Xs [64 * XS_STRIDE];
    __shared__ float Was[32 * 128];
    __shared__ float Wbs[32 * 128];

    int tid = threadIdx.x;
    int tx = tid & 15, ty = tid >> 4;
    int row0 = blockIdx.x * 64;

    unsigned long long accA[4][4], accB[4][4];
    #pragma unroll
    for (int r = 0; r < 4; r++)
        #pragma unroll
        for (int p = 0; p < 4; p++) { accA[r][p] = 0ull; accB[r][p] = 0ull; }

    for (int kt = 0; kt < 4; kt++) {
        int k0 = kt * 32;
        for (int i = tid; i < 64 * 8; i += 256) {
            int r = i >> 3, kk = i & 7;
            int gr = row0 + r;
            float4 v = make_float4(0.f, 0.f, 0.f, 0.f);
            if (gr < N_NODES) v = *(const float4*)&X[gr * D + k0 + kk * 4];
            *(float4*)&Xs[r * XS_STRIDE + kk * 4] = v;
        }
        {
            int c = tid & 127, half = tid >> 7;
            #pragma unroll
            for (int q = 0; q < 4; q++) {
                int kk4 = half * 4 + q;
                float4 va = *(const float4*)&Wa[c * D + k0 + kk4 * 4];
                float4 vb = *(const float4*)&Wb[c * D + k0 + kk4 * 4];
                Was[(kk4 * 4 + 0) * 128 + c] = va.x;
                Was[(kk4 * 4 + 1) * 128 + c] = va.y;
                Was[(kk4 * 4 + 2) * 128 + c] = va.z;
                Was[(kk4 * 4 + 3) * 128 + c] = va.w;
                Wbs[(kk4 * 4 + 0) * 128 + c] = vb.x;
                Wbs[(kk4 * 4 + 1) * 128 + c] = vb.y;
                Wbs[(kk4 * 4 + 2) * 128 + c] = vb.z;
                Wbs[(kk4 * 4 + 3) * 128 + c] = vb.w;
            }
        }
        __syncthreads();

        #pragma unroll
        for (int kk4 = 0; kk4 < 8; kk4++) {
            float4 xr[4];
            #pragma unroll
            for (int r = 0; r < 4; r++)
                xr[r] = *(float4*)&Xs[(ty * 4 + r) * XS_STRIDE + kk4 * 4];

            #define K_STEP(J, COMP)                                                        \
            {                                                                              \
                int kk = kk4 * 4 + J;                                                      \
                unsigned long long xx[4];                                                  \
                xx[0] = bcast2(xr[0].COMP); xx[1] = bcast2(xr[1].COMP);                    \
                xx[2] = bcast2(xr[2].COMP); xx[3] = bcast2(xr[3].COMP);                    \
                _Pragma("unroll")                                                          \
                for (int p = 0; p < 4; p++) {                                              \
                    unsigned long long wa = *(const unsigned long long*)&Was[kk * 128 + 32 * p + 2 * tx]; \
                    unsigned long long wb = *(const unsigned long long*)&Wbs[kk * 128 + 32 * p + 2 * tx]; \
                    _Pragma("unroll")                                                      \
                    for (int r = 0; r < 4; r++) {                                          \
                        ffma2(accA[r][p], xx[r], wa);                                      \
                        ffma2(accB[r][p], xx[r], wb);                                      \
                    }                                                                      \
                }                                                                          \
            }
            K_STEP(0, x)
            K_STEP(1, y)
            K_STEP(2, z)
            K_STEP(3, w)
            #undef K_STEP
        }
        __syncthreads();
    }

    #pragma unroll
    for (int p = 0; p < 4; p++) {
        int c = 32 * p + 2 * tx;
        float b0 = bias[c], b1 = bias[c + 1];
        #pragma unroll
        for (int r = 0; r < 4; r++) {
            int gr = row0 + ty * 4 + r;
            if (gr < N_NODES) {
                float a0, a1;
                // rel path: store as fp16x2 (gather stream)
                asm("mov.b64 {%0, %1}, %2;" : "=f"(a0), "=f"(a1) : "l"(accA[r][p]));
                g_Yh[gr * (D / 2) + (c >> 1)] = __float22half2_rn(make_float2(a0, a1));
                // root path: fp32
                asm("mov.b64 {%0, %1}, %2;" : "=f"(a0), "=f"(a1) : "l"(accB[r][p]));
                *(float2*)&Yb[gr * D + c] = make_float2(a0 + b0, a1 + b1);
            }
        }
    }
}

// ---------------- edge aggregation: H[i] += sum_e w_e * Yh[src_e] ----------
// one warp/node; each lane covers 4 cols = 2 half2 = one LDG.64 per edge
template <int MODE>   // 1: into g_H with relu; 2: into g_H2
__global__ void k_agg() {
    float* H = (MODE == 1) ? g_H : g_H2;
    int node = (blockIdx.x * blockDim.x + threadIdx.x) >> 5;
    int lane = threadIdx.x & 31;
    if (node >= N_NODES) return;
    int beg = g_off[node], end = g_off[node + 1];
    float4 acc = *(float4*)&H[node * D + lane * 4];
    int col2 = lane * 2;                      // half2 index within row
    int e = beg;
    for (; e + 8 <= end; e += 8) {
        int2 p[8];
        #pragma unroll
        for (int j = 0; j < 8; j++) p[j] = g_srcw[e + j];
        uint2 u[8];
        #pragma unroll
        for (int j = 0; j < 8; j++)
            u[j] = *(const uint2*)&g_Yh[p[j].x * (D / 2) + col2];
        #pragma unroll
        for (int j = 0; j < 8; j++) {
            float w = __int_as_float(p[j].y);
            float2 f0 = __half22float2(*(const __half2*)&u[j].x);
            float2 f1 = __half22float2(*(const __half2*)&u[j].y);
            acc.x += w * f0.x; acc.y += w * f0.y;
            acc.z += w * f1.x; acc.w += w * f1.y;
        }
    }
    for (; e < end; e++) {
        int2 pe = g_srcw[e];
        float w = __int_as_float(pe.y);
        uint2 u = *(const uint2*)&g_Yh[pe.x * (D / 2) + col2];
        float2 f0 = __half22float2(*(const __half2*)&u.x);
        float2 f1 = __half22float2(*(const __half2*)&u.y);
        acc.x += w * f0.x; acc.y += w * f0.y;
        acc.z += w * f1.x; acc.w += w * f1.y;
    }
    if (MODE == 1) {
        acc.x = fmaxf(acc.x, 0.f); acc.y = fmaxf(acc.y, 0.f);
        acc.z = fmaxf(acc.z, 0.f); acc.w = fmaxf(acc.w, 0.f);
    }
    *(float4*)&H[node * D + lane * 4] = acc;
}

// ---------------- mean-pool + linear head + relu ---------------------------
__global__ void k_pool(const int* __restrict__ batch,
                       const float* __restrict__ Wlin, const float* __restrict__ blin,
                       float* __restrict__ out) {
    const float* H2 = g_H2;
    int g = blockIdx.x;
    int c = threadIdx.x;   // 128 threads
    int lo = 0, hi = N_NODES;
    while (lo < hi) { int m = (lo + hi) >> 1; if (batch[m] < g) lo = m + 1; else hi = m; }
    int start = lo;
    lo = 0; hi = N_NODES;
    while (lo < hi) { int m = (lo + hi) >> 1; if (batch[m] < g + 1) lo = m + 1; else hi = m; }
    int end = lo;

    float a0 = 0.f, a1 = 0.f, a2 = 0.f, a3 = 0.f;
    int n = start;
    for (; n + 4 <= end; n += 4) {
        a0 += H2[n * D + c];
        a1 += H2[(n + 1) * D + c];
        a2 += H2[(n + 2) * D + c];
        a3 += H2[(n + 3) * D + c];
    }
    for (; n < end; n++) a0 += H2[n * D + c];
    float acc = (a0 + a1) + (a2 + a3);
    float cnt = (float)(end - start);
    float pooled = acc / fmaxf(cnt, 1.f);
    float v = pooled * Wlin[c];

    __shared__ float red[128];
    red[c] = v;
    __syncthreads();
    for (int s = 64; s > 0; s >>= 1) {
        if (c < s) red[c] += red[c + s];
        __syncthreads();
    }
    if (c == 0) out[g] = fmaxf(red[0] + blin[0], 0.f);
}

// ---------------- launch ---------------------------------------------------
extern "C" void kernel_launch(void* const* d_in, const int* in_sizes, int n_in,
                              void* d_out, int out_size) {
    const float* x      = (const float*)d_in[0];
    const int*   ei     = (const int*)d_in[1];
    const int*   batch  = (const int*)d_in[2];
    const float* ew     = (const float*)d_in[3];
    const float* W1_rel = (const float*)d_in[4];
    const float* b1     = (const float*)d_in[5];
    const float* W1_root= (const float*)d_in[6];
    const float* W3_rel = (const float*)d_in[7];
    const float* b3     = (const float*)d_in[8];
    const float* W3_root= (const float*)d_in[9];
    const float* Wlin   = (const float*)d_in[10];
    const float* blin   = (const float*)d_in[11];
    float*       out    = (float*)d_out;

    int gb = (N_NODES + 63) / 64;

    cudaStream_t side = nullptr;
    cudaEvent_t evFork = nullptr, evJoin = nullptr;
    bool forked = (cudaStreamCreateWithFlags(&side, cudaStreamNonBlocking) == cudaSuccess) &&
                  (cudaEventCreateWithFlags(&evFork, cudaEventDisableTiming) == cudaSuccess) &&
                  (cudaEventCreateWithFlags(&evJoin, cudaEventDisableTiming) == cudaSuccess);

    if (forked && cudaEventRecord(evFork, 0) == cudaSuccess &&
        cudaStreamWaitEvent(side, evFork, 0) == cudaSuccess) {
        // Branch A (main): layer-1 dual GEMM
        k_gemm2<0><<<gb, 256>>>(x, W1_rel, W1_root, b1);
        // Branch B (side): CSR build
        k_zero <<<(N_PAD + 255) / 256, 256, 0, side>>>();
        k_hist <<<(N_EDGES + 255) / 256, 256, 0, side>>>(ei);
        k_scan <<<1, 1024, 0, side>>>();
        k_place<<<(N_EDGES / 4 + 255) / 256, 256, 0, side>>>(ei, ew);
        cudaEventRecord(evJoin, side);
        cudaStreamWaitEvent(0, evJoin, 0);
    } else {
        k_zero <<<(N_PAD + 255) / 256, 256>>>();
        k_hist <<<(N_EDGES + 255) / 256, 256>>>(ei);
        k_scan <<<1, 1024>>>();
        k_place<<<(N_EDGES / 4 + 255) / 256, 256>>>(ei, ew);
        k_gemm2<0><<<gb, 256>>>(x, W1_rel, W1_root, b1);
    }

    // layer 1 aggregation
    k_agg<1><<<(N_NODES * 32 + 255) / 256, 256>>>();

    // layer 2
    k_gemm2<1><<<gb, 256>>>(nullptr, W3_rel, W3_root, b3);
    k_agg<2><<<(N_NODES * 32 + 255) / 256, 256>>>();

    // pool + head
    k_pool<<<NGRAPH, 128>>>(batch, Wlin, blin, out);
}